// round 2
// baseline (speedup 1.0000x reference)
#include <cuda_runtime.h>

#define NB 8
#define NM 512
#define ND 64
#define TILE_I 32
#define CHUNK_J 64
#define THREADS 256
#define KSTRIDE 68          // padded row stride (floats) for k/v tiles
#define SSTRIDE 516         // padded row stride (floats) for the score matrix

// shared layout (floats)
#define OFF_SCORES 0
#define OFF_VI     (TILE_I * SSTRIDE)                    // 16512
#define OFF_KJ     (OFF_VI + TILE_I * KSTRIDE)           // 18688
#define OFF_INV    (OFF_KJ + CHUNK_J * KSTRIDE)          // 23040
#define SMEM_FLOATS (OFF_INV + TILE_I)                   // 23072
#define SMEM_BYTES  (SMEM_FLOATS * 4)                    // 92288

__global__ __launch_bounds__(THREADS, 1)
void laplace_attn_kernel(const float* __restrict__ k,
                         const float* __restrict__ v,
                         float* __restrict__ out) {
    extern __shared__ float smem[];
    float* s_scores = smem + OFF_SCORES;   // [TILE_I][SSTRIDE]
    float* s_vi     = smem + OFF_VI;       // [TILE_I][KSTRIDE]
    float* s_kj     = smem + OFF_KJ;       // [CHUNK_J][KSTRIDE]
    float* s_inv    = smem + OFF_INV;      // [TILE_I]

    const int tid = threadIdx.x;
    const int b  = blockIdx.x / (NM / TILE_I);
    const int i0 = (blockIdx.x % (NM / TILE_I)) * TILE_I;

    // ---- stage v rows for this i-tile (the "query" side of the distance) ----
    {
        const float4* src = (const float4*)(v + (size_t)(b * NM + i0) * ND);
        for (int e = tid; e < TILE_I * ND / 4; e += THREADS) {
            int idx = e * 4;
            int row = idx / ND, col = idx % ND;
            *(float4*)&s_vi[row * KSTRIDE + col] = src[e];
        }
    }
    __syncthreads();

    // ---- Pass A: scores[i][j] = 0.5 * sum_d |k[b,j,d] - v[b,i,d]| ----
    const int tx = tid & 15;           // j direction (16 lanes)
    const int ty = tid >> 4;           // i direction (16 groups)
    const int ia = ty * 2;             // this thread's two local i rows

    for (int jc = 0; jc < NM; jc += CHUNK_J) {
        // stage k chunk
        {
            const float4* src = (const float4*)(k + (size_t)(b * NM + jc) * ND);
            for (int e = tid; e < CHUNK_J * ND / 4; e += THREADS) {
                int idx = e * 4;
                int row = idx / ND, col = idx % ND;
                *(float4*)&s_kj[row * KSTRIDE + col] = src[e];
            }
        }
        __syncthreads();

        float acc0[4] = {0.f, 0.f, 0.f, 0.f};
        float acc1[4] = {0.f, 0.f, 0.f, 0.f};

        #pragma unroll
        for (int d = 0; d < ND; d += 4) {
            float4 a0 = *(const float4*)&s_vi[ia * KSTRIDE + d];
            float4 a1 = *(const float4*)&s_vi[(ia + 1) * KSTRIDE + d];
            #pragma unroll
            for (int jj = 0; jj < 4; ++jj) {
                float4 kb = *(const float4*)&s_kj[(tx + 16 * jj) * KSTRIDE + d];
                acc0[jj] += fabsf(a0.x - kb.x) + fabsf(a0.y - kb.y)
                          + fabsf(a0.z - kb.z) + fabsf(a0.w - kb.w);
                acc1[jj] += fabsf(a1.x - kb.x) + fabsf(a1.y - kb.y)
                          + fabsf(a1.z - kb.z) + fabsf(a1.w - kb.w);
            }
        }
        #pragma unroll
        for (int jj = 0; jj < 4; ++jj) {
            int j = jc + tx + 16 * jj;
            s_scores[ia * SSTRIDE + j]       = 0.5f * acc0[jj];
            s_scores[(ia + 1) * SSTRIDE + j] = 0.5f * acc1[jj];
        }
        __syncthreads();
    }

    // ---- softmax over j per row (normalization deferred via s_inv) ----
    {
        const int warp = tid >> 5, lane = tid & 31;
        for (int r = warp; r < TILE_I; r += (THREADS / 32)) {
            float mx = -1e30f;
            for (int j = lane; j < NM; j += 32)
                mx = fmaxf(mx, s_scores[r * SSTRIDE + j]);
            #pragma unroll
            for (int off = 16; off > 0; off >>= 1)
                mx = fmaxf(mx, __shfl_xor_sync(0xffffffffu, mx, off));

            float sum = 0.f;
            for (int j = lane; j < NM; j += 32) {
                float e = __expf(s_scores[r * SSTRIDE + j] - mx);
                s_scores[r * SSTRIDE + j] = e;
                sum += e;
            }
            #pragma unroll
            for (int off = 16; off > 0; off >>= 1)
                sum += __shfl_xor_sync(0xffffffffu, sum, off);

            if (lane == 0) s_inv[r] = 1.f / sum;
        }
    }
    __syncthreads();

    // ---- Pass B: rep[i][d] = inv[i] * sum_j e[i][j] * v[b,j,d] ----
    const int dx = (tid & 15) * 4;     // this thread's d-quad
    const int ib = (tid >> 4) * 2;     // this thread's two local i rows
    float4 o0 = make_float4(0.f, 0.f, 0.f, 0.f);
    float4 o1 = make_float4(0.f, 0.f, 0.f, 0.f);

    for (int jc = 0; jc < NM; jc += CHUNK_J) {
        __syncthreads();   // previous consumers of s_kj done
        {
            const float4* src = (const float4*)(v + (size_t)(b * NM + jc) * ND);
            for (int e = tid; e < CHUNK_J * ND / 4; e += THREADS) {
                int idx = e * 4;
                int row = idx / ND, col = idx % ND;
                *(float4*)&s_kj[row * KSTRIDE + col] = src[e];
            }
        }
        __syncthreads();

        #pragma unroll 8
        for (int j = 0; j < CHUNK_J; ++j) {
            float w0 = s_scores[ib * SSTRIDE + jc + j];
            float w1 = s_scores[(ib + 1) * SSTRIDE + jc + j];
            float4 vv = *(const float4*)&s_kj[j * KSTRIDE + dx];
            o0.x += w0 * vv.x; o0.y += w0 * vv.y; o0.z += w0 * vv.z; o0.w += w0 * vv.w;
            o1.x += w1 * vv.x; o1.y += w1 * vv.y; o1.z += w1 * vv.z; o1.w += w1 * vv.w;
        }
    }

    const float inv0 = s_inv[ib];
    const float inv1 = s_inv[ib + 1];
    o0.x *= inv0; o0.y *= inv0; o0.z *= inv0; o0.w *= inv0;
    o1.x *= inv1; o1.y *= inv1; o1.z *= inv1; o1.w *= inv1;

    float* dst0 = out + (size_t)(b * NM + i0 + ib) * ND + dx;
    float* dst1 = out + (size_t)(b * NM + i0 + ib + 1) * ND + dx;
    *(float4*)dst0 = o0;
    *(float4*)dst1 = o1;
}

extern "C" void kernel_launch(void* const* d_in, const int* in_sizes, int n_in,
                              void* d_out, int out_size) {
    const float* k = (const float*)d_in[0];
    const float* v = (const float*)d_in[1];
    // q (d_in[2]) is unused by the reference computation.
    (void)in_sizes; (void)n_in; (void)out_size;

    cudaFuncSetAttribute(laplace_attn_kernel,
                         cudaFuncAttributeMaxDynamicSharedMemorySize, SMEM_BYTES);

    dim3 grid(NB * (NM / TILE_I));
    laplace_attn_kernel<<<grid, THREADS, SMEM_BYTES>>>(k, v, (float*)d_out);
}